// round 1
// baseline (speedup 1.0000x reference)
#include <cuda_runtime.h>
#include <math.h>

#define N_SRC1 200000
#define N_TGT1 50000
#define N_TGT2 10000
#define F_IN   256
#define F_HID  192
#define F_OUT  128
#define E1_MAX 1000000
#define E2_MAX 300000

// ---------------- scratch (static device globals; no allocs allowed) ----------------
__device__ float g_mean1[N_TGT1 * F_IN];    // 51.2 MB
__device__ float g_h1[N_TGT1 * F_HID];      // 38.4 MB
__device__ float g_mean2[N_TGT2 * F_HID];   // 7.7 MB
__device__ float g_h2[N_TGT2 * F_HID];      // 7.7 MB
__device__ float g_logits[N_TGT2 * F_OUT];  // 5.1 MB
__device__ int   g_cnt[N_TGT1];
__device__ int   g_offs1[N_TGT1 + 1];
__device__ int   g_offs2[N_TGT2 + 1];
__device__ int   g_csr1[E1_MAX];
__device__ int   g_csr2[E2_MAX];

// ---------------- CSR build ----------------
__global__ void hist_kernel(const int* __restrict__ tgt, int E, int* __restrict__ cnt) {
    int i = blockIdx.x * blockDim.x + threadIdx.x;
    if (i < E) atomicAdd(&cnt[tgt[i]], 1);
}

// single-block exclusive scan over n counts -> offs[0..n]
__global__ void scan_kernel(const int* __restrict__ cnt, int* __restrict__ offs, int n) {
    __shared__ int sm[1024];
    int tid = threadIdx.x;
    int chunk = (n + 1023) >> 10;
    int begin = tid * chunk;
    int end = begin + chunk; if (end > n) end = n;
    int sum = 0;
    for (int i = begin; i < end; i++) sum += cnt[i];
    sm[tid] = sum;
    __syncthreads();
    for (int off = 1; off < 1024; off <<= 1) {
        int v = (tid >= off) ? sm[tid - off] : 0;
        __syncthreads();
        sm[tid] += v;
        __syncthreads();
    }
    int run = sm[tid] - sum;   // exclusive prefix
    for (int i = begin; i < end; i++) { offs[i] = run; run += cnt[i]; }
    if (tid == 1023) offs[n] = sm[1023];
}

__global__ void fill_kernel(const int* __restrict__ src, const int* __restrict__ tgt, int E,
                            const int* __restrict__ offs, int* __restrict__ cursor,
                            int* __restrict__ csr) {
    int i = blockIdx.x * blockDim.x + threadIdx.x;
    if (i < E) {
        int t = tgt[i];
        int p = atomicAdd(&cursor[t], 1);
        csr[offs[t] + p] = src[i];
    }
}

// ---------------- segment mean (node-parallel, no float atomics) ----------------
template <int F>
__global__ void aggregate_mean_kernel(const float* __restrict__ X,
                                      const int* __restrict__ csr,
                                      const int* __restrict__ offs,
                                      float* __restrict__ out) {
    int node = blockIdx.x;
    int s = offs[node], e = offs[node + 1];
    int t = threadIdx.x;
    float acc = 0.0f;
    int j = s;
    for (; j + 1 < e; j += 2) {
        int s0 = __ldg(&csr[j]);
        int s1 = __ldg(&csr[j + 1]);
        acc += X[s0 * F + t] + X[s1 * F + t];
    }
    if (j < e) {
        int s0 = __ldg(&csr[j]);
        acc += X[s0 * F + t];
    }
    int deg = e - s;
    float inv = 1.0f / (float)(deg > 1 ? deg : 1);
    out[node * F + t] = acc * inv;
}

// ---------------- fused dual-A tiled GEMM: C = act(A1@W1^T [+ A2@W2^T] + bias) ----------------
// BM=128, BN=64, BK=16, 256 threads, 8x4 per thread. W stored [N,K] row-major.
template <int K, bool RELU_A>
__device__ __forceinline__ void gemm_phase(const float* __restrict__ A,
                                           const float* __restrict__ W,
                                           int M, int m0, int n0, int tid,
                                           float (&As)[16][132], float (&Ws)[16][68],
                                           float (&acc)[8][4]) {
    const int arow = tid >> 2;          // 0..63
    const int ak = (tid & 3) << 2;      // 0,4,8,12
    const int ty = tid >> 4;            // 0..15
    const int tx = tid & 15;            // 0..15
    for (int kt = 0; kt < K; kt += 16) {
        float4 av0 = make_float4(0.f, 0.f, 0.f, 0.f);
        float4 av1 = av0;
        int r0 = m0 + arow, r1 = r0 + 64;
        if (r0 < M) av0 = *(const float4*)&A[r0 * K + kt + ak];
        if (r1 < M) av1 = *(const float4*)&A[r1 * K + kt + ak];
        if (RELU_A) {
            av0.x = fmaxf(av0.x, 0.f); av0.y = fmaxf(av0.y, 0.f);
            av0.z = fmaxf(av0.z, 0.f); av0.w = fmaxf(av0.w, 0.f);
            av1.x = fmaxf(av1.x, 0.f); av1.y = fmaxf(av1.y, 0.f);
            av1.z = fmaxf(av1.z, 0.f); av1.w = fmaxf(av1.w, 0.f);
        }
        float4 wv = *(const float4*)&W[(n0 + arow) * K + kt + ak];
        __syncthreads();
        As[ak + 0][arow] = av0.x; As[ak + 1][arow] = av0.y;
        As[ak + 2][arow] = av0.z; As[ak + 3][arow] = av0.w;
        As[ak + 0][arow + 64] = av1.x; As[ak + 1][arow + 64] = av1.y;
        As[ak + 2][arow + 64] = av1.z; As[ak + 3][arow + 64] = av1.w;
        Ws[ak + 0][arow] = wv.x; Ws[ak + 1][arow] = wv.y;
        Ws[ak + 2][arow] = wv.z; Ws[ak + 3][arow] = wv.w;
        __syncthreads();
#pragma unroll
        for (int kk = 0; kk < 16; kk++) {
            float a[8], b[4];
#pragma unroll
            for (int i = 0; i < 8; i++) a[i] = As[kk][ty * 8 + i];
#pragma unroll
            for (int jj = 0; jj < 4; jj++) b[jj] = Ws[kk][tx * 4 + jj];
#pragma unroll
            for (int i = 0; i < 8; i++)
#pragma unroll
                for (int jj = 0; jj < 4; jj++) acc[i][jj] += a[i] * b[jj];
        }
    }
}

template <int K1, int K2, bool RELU_A, bool RELU_OUT>
__global__ __launch_bounds__(256) void gemm_kernel(const float* __restrict__ A1,
                                                   const float* __restrict__ A2,
                                                   const float* __restrict__ W1,
                                                   const float* __restrict__ W2,
                                                   const float* __restrict__ bias,
                                                   float* __restrict__ C, int M, int N) {
    __shared__ float As[16][132];
    __shared__ float Ws[16][68];
    float acc[8][4];
#pragma unroll
    for (int i = 0; i < 8; i++)
#pragma unroll
        for (int j = 0; j < 4; j++) acc[i][j] = 0.f;

    int m0 = blockIdx.x * 128;
    int n0 = blockIdx.y * 64;
    int tid = threadIdx.x;

    gemm_phase<K1, RELU_A>(A1, W1, M, m0, n0, tid, As, Ws, acc);
    if constexpr (K2 > 0) gemm_phase<K2, false>(A2, W2, M, m0, n0, tid, As, Ws, acc);

    int ty = tid >> 4, tx = tid & 15;
    float4 bv = *(const float4*)&bias[n0 + tx * 4];
#pragma unroll
    for (int i = 0; i < 8; i++) {
        int row = m0 + ty * 8 + i;
        if (row < M) {
            float4 r;
            r.x = acc[i][0] + bv.x;
            r.y = acc[i][1] + bv.y;
            r.z = acc[i][2] + bv.z;
            r.w = acc[i][3] + bv.w;
            if (RELU_OUT) {
                r.x = fmaxf(r.x, 0.f); r.y = fmaxf(r.y, 0.f);
                r.z = fmaxf(r.z, 0.f); r.w = fmaxf(r.w, 0.f);
            }
            *(float4*)&C[row * N + n0 + tx * 4] = r;
        }
    }
}

// ---------------- log_softmax over rows of 128 ----------------
__global__ void logsoftmax_kernel(const float* __restrict__ logits, float* __restrict__ out) {
    __shared__ float red[128];
    int row = blockIdx.x;
    int t = threadIdx.x;
    float v = logits[row * F_OUT + t];
    red[t] = v;
    __syncthreads();
    for (int off = 64; off > 0; off >>= 1) {
        if (t < off) red[t] = fmaxf(red[t], red[t + off]);
        __syncthreads();
    }
    float mx = red[0];
    __syncthreads();
    red[t] = expf(v - mx);
    __syncthreads();
    for (int off = 64; off > 0; off >>= 1) {
        if (t < off) red[t] += red[t + off];
        __syncthreads();
    }
    float lse = logf(red[0]);
    out[row * F_OUT + t] = v - mx - lse;
}

// ---------------- launch ----------------
extern "C" void kernel_launch(void* const* d_in, const int* in_sizes, int n_in,
                              void* d_out, int out_size) {
    const float* x   = (const float*)d_in[0];
    const int*   ei1 = (const int*)d_in[1];
    const int*   ei2 = (const int*)d_in[2];
    const float* Wl1 = (const float*)d_in[3];
    const float* bl1 = (const float*)d_in[4];
    const float* Wr1 = (const float*)d_in[5];
    const float* Wl2 = (const float*)d_in[6];
    const float* bl2 = (const float*)d_in[7];
    const float* Wr2 = (const float*)d_in[8];
    const float* W1  = (const float*)d_in[9];
    const float* b1  = (const float*)d_in[10];
    const float* W2  = (const float*)d_in[11];
    const float* b2  = (const float*)d_in[12];

    int E1 = in_sizes[1] / 2;
    int E2 = in_sizes[2] / 2;
    const int* src1 = ei1;
    const int* tgt1 = ei1 + E1;
    const int* src2 = ei2;
    const int* tgt2 = ei2 + E2;

    float* out_ls  = (float*)d_out;                      // [10000,128] log_softmax
    float* out_emb = (float*)d_out + N_TGT2 * F_OUT;     // [10000,192] embedding

    float *p_mean1, *p_h1, *p_mean2, *p_h2, *p_logits;
    int *p_cnt, *p_offs1, *p_offs2, *p_csr1, *p_csr2;
    cudaGetSymbolAddress((void**)&p_mean1,  g_mean1);
    cudaGetSymbolAddress((void**)&p_h1,     g_h1);
    cudaGetSymbolAddress((void**)&p_mean2,  g_mean2);
    cudaGetSymbolAddress((void**)&p_h2,     g_h2);
    cudaGetSymbolAddress((void**)&p_logits, g_logits);
    cudaGetSymbolAddress((void**)&p_cnt,    g_cnt);
    cudaGetSymbolAddress((void**)&p_offs1,  g_offs1);
    cudaGetSymbolAddress((void**)&p_offs2,  g_offs2);
    cudaGetSymbolAddress((void**)&p_csr1,   g_csr1);
    cudaGetSymbolAddress((void**)&p_csr2,   g_csr2);

    // ---- layer 1: CSR build + mean aggregate over x ----
    cudaMemsetAsync(p_cnt, 0, N_TGT1 * sizeof(int));
    hist_kernel<<<(E1 + 255) / 256, 256>>>(tgt1, E1, p_cnt);
    scan_kernel<<<1, 1024>>>(p_cnt, p_offs1, N_TGT1);
    cudaMemsetAsync(p_cnt, 0, N_TGT1 * sizeof(int));
    fill_kernel<<<(E1 + 255) / 256, 256>>>(src1, tgt1, E1, p_offs1, p_cnt, p_csr1);
    aggregate_mean_kernel<F_IN><<<N_TGT1, F_IN>>>(x, p_csr1, p_offs1, p_mean1);

    // h1 = relu(mean1 @ Wl1^T + bl1 + x[:50000] @ Wr1^T)
    gemm_kernel<F_IN, F_IN, false, true>
        <<<dim3((N_TGT1 + 127) / 128, F_HID / 64), 256>>>(
            p_mean1, x, Wl1, Wr1, bl1, p_h1, N_TGT1, F_HID);

    // ---- layer 2 ----
    cudaMemsetAsync(p_cnt, 0, N_TGT2 * sizeof(int));
    hist_kernel<<<(E2 + 255) / 256, 256>>>(tgt2, E2, p_cnt);
    scan_kernel<<<1, 1024>>>(p_cnt, p_offs2, N_TGT2);
    cudaMemsetAsync(p_cnt, 0, N_TGT2 * sizeof(int));
    fill_kernel<<<(E2 + 255) / 256, 256>>>(src2, tgt2, E2, p_offs2, p_cnt, p_csr2);
    aggregate_mean_kernel<F_HID><<<N_TGT2, F_HID>>>(p_h1, p_csr2, p_offs2, p_mean2);

    // h2 = relu(mean2 @ Wl2^T + bl2 + h1[:10000] @ Wr2^T)
    gemm_kernel<F_HID, F_HID, false, true>
        <<<dim3((N_TGT2 + 127) / 128, F_HID / 64), 256>>>(
            p_mean2, p_h1, Wl2, Wr2, bl2, p_h2, N_TGT2, F_HID);

    // embedding = h2 @ W1^T + b1  (written straight into d_out)
    gemm_kernel<F_HID, 0, false, false>
        <<<dim3((N_TGT2 + 127) / 128, F_HID / 64), 256>>>(
            p_h2, nullptr, W1, nullptr, b1, out_emb, N_TGT2, F_HID);

    // logits = relu(embedding) @ W2^T + b2
    gemm_kernel<F_HID, 0, true, false>
        <<<dim3((N_TGT2 + 127) / 128, F_OUT / 64), 256>>>(
            out_emb, nullptr, W2, nullptr, b2, p_logits, N_TGT2, F_OUT);

    logsoftmax_kernel<<<N_TGT2, F_OUT>>>(p_logits, out_ls);
}

// round 2
// speedup vs baseline: 1.0896x; 1.0896x over previous
#include <cuda_runtime.h>
#include <cuda_bf16.h>
#include <math.h>
#include <stdint.h>

typedef __nv_bfloat16 bf16;

#define N_SRC1 200000
#define N_TGT1 50000
#define N_TGT2 10000
#define F_IN   256
#define F_HID  192
#define F_OUT  128
#define E1_MAX 1000000
#define E2_MAX 300000

// ---------------- scratch (static device globals; no allocs allowed) ----------------
__device__ bf16 g_x_hi[N_TGT1 * F_IN];
__device__ bf16 g_x_lo[N_TGT1 * F_IN];
__device__ bf16 g_m1_hi[N_TGT1 * F_IN];
__device__ bf16 g_m1_lo[N_TGT1 * F_IN];
__device__ float g_h1[(size_t)N_TGT1 * F_HID];
__device__ bf16 g_h1_hi[N_TGT2 * F_HID];
__device__ bf16 g_h1_lo[N_TGT2 * F_HID];
__device__ bf16 g_m2_hi[N_TGT2 * F_HID];
__device__ bf16 g_m2_lo[N_TGT2 * F_HID];
__device__ bf16 g_h2_hi[N_TGT2 * F_HID];
__device__ bf16 g_h2_lo[N_TGT2 * F_HID];
__device__ bf16 g_er_hi[N_TGT2 * F_HID];
__device__ bf16 g_er_lo[N_TGT2 * F_HID];
__device__ float g_logits[N_TGT2 * F_OUT];
// weight hi/lo planes
__device__ bf16 g_wl1_hi[F_HID * F_IN],  g_wl1_lo[F_HID * F_IN];
__device__ bf16 g_wr1_hi[F_HID * F_IN],  g_wr1_lo[F_HID * F_IN];
__device__ bf16 g_wl2_hi[F_HID * F_HID], g_wl2_lo[F_HID * F_HID];
__device__ bf16 g_wr2_hi[F_HID * F_HID], g_wr2_lo[F_HID * F_HID];
__device__ bf16 g_w1_hi[F_HID * F_HID],  g_w1_lo[F_HID * F_HID];
__device__ bf16 g_w2_hi[F_OUT * F_HID],  g_w2_lo[F_OUT * F_HID];
// CSR
__device__ int g_cnt[N_TGT1];
__device__ int g_offs1[N_TGT1 + 1];
__device__ int g_offs2[N_TGT2 + 1];
__device__ int g_csr1[E1_MAX];
__device__ int g_csr2[E2_MAX];

// ---------------- CSR build ----------------
__global__ void hist_kernel(const int* __restrict__ tgt, int E, int* __restrict__ cnt) {
    int i = blockIdx.x * blockDim.x + threadIdx.x;
    if (i < E) atomicAdd(&cnt[tgt[i]], 1);
}

__global__ void scan_kernel(const int* __restrict__ cnt, int* __restrict__ offs, int n) {
    __shared__ int sm[1024];
    int tid = threadIdx.x;
    int chunk = (n + 1023) >> 10;
    int begin = tid * chunk;
    int end = begin + chunk; if (end > n) end = n;
    int sum = 0;
    for (int i = begin; i < end; i++) sum += cnt[i];
    sm[tid] = sum;
    __syncthreads();
    for (int off = 1; off < 1024; off <<= 1) {
        int v = (tid >= off) ? sm[tid - off] : 0;
        __syncthreads();
        sm[tid] += v;
        __syncthreads();
    }
    int run = sm[tid] - sum;
    for (int i = begin; i < end; i++) { offs[i] = run; run += cnt[i]; }
    if (tid == 1023) offs[n] = sm[1023];
}

__global__ void fill_kernel(const int* __restrict__ src, const int* __restrict__ tgt, int E,
                            const int* __restrict__ offs, int* __restrict__ cursor,
                            int* __restrict__ csr) {
    int i = blockIdx.x * blockDim.x + threadIdx.x;
    if (i < E) {
        int t = tgt[i];
        int p = atomicAdd(&cursor[t], 1);
        csr[offs[t] + p] = src[i];
    }
}

// ---------------- splits ----------------
__device__ __forceinline__ void split2(float v, bf16& h, bf16& l) {
    bf16 hh = __float2bfloat16_rn(v);
    h = hh;
    l = __float2bfloat16_rn(v - __bfloat162float(hh));
}

__global__ void split_x_kernel(const float* __restrict__ x) {
    int i = blockIdx.x * 256 + threadIdx.x;
    if (i < N_TGT1 * F_IN) {
        bf16 h, l; split2(x[i], h, l);
        g_x_hi[i] = h; g_x_lo[i] = l;
    }
}

__global__ void split_weights_kernel(const float* __restrict__ wl1, const float* __restrict__ wr1,
                                     const float* __restrict__ wl2, const float* __restrict__ wr2,
                                     const float* __restrict__ w1,  const float* __restrict__ w2) {
    int i = blockIdx.x * 256 + threadIdx.x;
    const int A = F_HID * F_IN;    // 49152
    const int B = F_HID * F_HID;   // 36864
    const int C = F_OUT * F_HID;   // 24576
    float v; bf16 *hp, *lp; int o;
    if      (i < A)             { o = i;               v = wl1[o]; hp = g_wl1_hi; lp = g_wl1_lo; }
    else if (i < 2*A)           { o = i - A;           v = wr1[o]; hp = g_wr1_hi; lp = g_wr1_lo; }
    else if (i < 2*A + B)       { o = i - 2*A;         v = wl2[o]; hp = g_wl2_hi; lp = g_wl2_lo; }
    else if (i < 2*A + 2*B)     { o = i - 2*A - B;     v = wr2[o]; hp = g_wr2_hi; lp = g_wr2_lo; }
    else if (i < 2*A + 3*B)     { o = i - 2*A - 2*B;   v = w1[o];  hp = g_w1_hi;  lp = g_w1_lo; }
    else if (i < 2*A + 3*B + C) { o = i - 2*A - 3*B;   v = w2[o];  hp = g_w2_hi;  lp = g_w2_lo; }
    else return;
    bf16 h, l; split2(v, h, l);
    hp[o] = h; lp[o] = l;
}

// ---------------- segment mean -> hi/lo planes ----------------
template <int F>
__global__ void aggregate_hilo(const float* __restrict__ X, const int* __restrict__ csr,
                               const int* __restrict__ offs,
                               bf16* __restrict__ hi, bf16* __restrict__ lo) {
    int node = blockIdx.x;
    int t = threadIdx.x;
    int s = offs[node], e = offs[node + 1];
    float acc = 0.0f;
    int j = s;
    for (; j + 3 < e; j += 4) {
        int i0 = __ldg(&csr[j]),     i1 = __ldg(&csr[j + 1]);
        int i2 = __ldg(&csr[j + 2]), i3 = __ldg(&csr[j + 3]);
        float v0 = X[(size_t)i0 * F + t];
        float v1 = X[(size_t)i1 * F + t];
        float v2 = X[(size_t)i2 * F + t];
        float v3 = X[(size_t)i3 * F + t];
        acc += (v0 + v1) + (v2 + v3);
    }
    for (; j < e; j++) acc += X[(size_t)__ldg(&csr[j]) * F + t];
    int deg = e - s;
    float m = acc * (1.0f / (float)(deg > 1 ? deg : 1));
    bf16 h, l; split2(m, h, l);
    size_t o = (size_t)node * F + t;
    hi[o] = h; lo[o] = l;
}

// ---------------- bf16x3 tensor-core GEMM: C = act(A1@W1^T [+ A2@W2^T] + bias) ----------------
// Block 128x64, BK=32, 256 threads (8 warps as 4x2), warp tile 32x32, mma m16n8k16.
#define BM 128
#define BN 64
#define BKT 32
#define SLDA 40   // BK + 8 pad (bf16 elems): conflict-free ldmatrix

__device__ __forceinline__ void ldsm4(uint32_t r[4], uint32_t addr) {
    asm volatile("ldmatrix.sync.aligned.m8n8.x4.shared.b16 {%0,%1,%2,%3}, [%4];"
                 : "=r"(r[0]), "=r"(r[1]), "=r"(r[2]), "=r"(r[3]) : "r"(addr));
}
__device__ __forceinline__ void mma_bf16(float d[4], const uint32_t a[4], uint32_t b0, uint32_t b1) {
    asm volatile("mma.sync.aligned.m16n8k16.row.col.f32.bf16.bf16.f32 "
                 "{%0,%1,%2,%3},{%4,%5,%6,%7},{%8,%9},{%0,%1,%2,%3};"
                 : "+f"(d[0]), "+f"(d[1]), "+f"(d[2]), "+f"(d[3])
                 : "r"(a[0]), "r"(a[1]), "r"(a[2]), "r"(a[3]), "r"(b0), "r"(b1));
}

template <int K>
__device__ __forceinline__ void mma_phase(const bf16* __restrict__ Ahi, const bf16* __restrict__ Alo,
                                          const bf16* __restrict__ Whi, const bf16* __restrict__ Wlo,
                                          int M, int m0, int n0,
                                          bf16 (*sA)[SLDA], bf16 (*sW)[SLDA],
                                          float acc[2][4][4]) {
    int t = threadIdx.x;
    int lane = t & 31, warp = t >> 5;
    int wm = (warp & 3) * 32, wn = (warp >> 2) * 32;
    uint32_t sA_u = (uint32_t)__cvta_generic_to_shared(&sA[0][0]);
    uint32_t sW_u = (uint32_t)__cvta_generic_to_shared(&sW[0][0]);

    // loader indices
    int ar = t >> 1, ac = (t & 1) * 16;   // A: 128 rows x 32 cols per plane
    int wr = t >> 2, wc = (t & 3) * 8;    // W: 64 rows x 32 cols per plane

    // ldmatrix byte offsets at ks=0
    uint32_t a_off[2][2], b_off[2][2];
#pragma unroll
    for (int p = 0; p < 2; p++) {
#pragma unroll
        for (int mf = 0; mf < 2; mf++)
            a_off[p][mf] = sA_u + (uint32_t)(((p * BM + wm + mf * 16 + (lane & 15)) * SLDA + ((lane >> 4) * 8)) * 2);
#pragma unroll
        for (int np = 0; np < 2; np++)
            b_off[p][np] = sW_u + (uint32_t)(((p * BN + wn + np * 16 + (lane & 7) + ((lane >> 4) * 8)) * SLDA +
                                             (((lane >> 3) & 1) * 8)) * 2);
    }

    for (int kt = 0; kt < K; kt += BKT) {
        __syncthreads();
        {
            bool av = (m0 + ar) < M;
            uint4 z = make_uint4(0, 0, 0, 0);
            size_t abase = (size_t)(m0 + ar) * K + kt + ac;
            uint4 h0 = av ? *(const uint4*)(Ahi + abase)     : z;
            uint4 h1 = av ? *(const uint4*)(Ahi + abase + 8) : z;
            uint4 l0 = av ? *(const uint4*)(Alo + abase)     : z;
            uint4 l1 = av ? *(const uint4*)(Alo + abase + 8) : z;
            *(uint4*)&sA[ar][ac]           = h0;
            *(uint4*)&sA[ar][ac + 8]       = h1;
            *(uint4*)&sA[BM + ar][ac]      = l0;
            *(uint4*)&sA[BM + ar][ac + 8]  = l1;
            size_t wbase = (size_t)(n0 + wr) * K + kt + wc;
            *(uint4*)&sW[wr][wc]      = *(const uint4*)(Whi + wbase);
            *(uint4*)&sW[BN + wr][wc] = *(const uint4*)(Wlo + wbase);
        }
        __syncthreads();
#pragma unroll
        for (int ks = 0; ks < 2; ks++) {
            uint32_t a[2][2][4], b[2][2][4];
#pragma unroll
            for (int p = 0; p < 2; p++) {
#pragma unroll
                for (int mf = 0; mf < 2; mf++) ldsm4(a[p][mf], a_off[p][mf] + ks * 32);
#pragma unroll
                for (int np = 0; np < 2; np++) ldsm4(b[p][np], b_off[p][np] + ks * 32);
            }
#pragma unroll
            for (int mf = 0; mf < 2; mf++)
#pragma unroll
                for (int nf = 0; nf < 4; nf++) {
                    uint32_t bh0 = b[0][nf >> 1][(nf & 1) * 2], bh1 = b[0][nf >> 1][(nf & 1) * 2 + 1];
                    uint32_t bl0 = b[1][nf >> 1][(nf & 1) * 2], bl1 = b[1][nf >> 1][(nf & 1) * 2 + 1];
                    mma_bf16(acc[mf][nf], a[0][mf], bh0, bh1);  // hi*hi
                    mma_bf16(acc[mf][nf], a[0][mf], bl0, bl1);  // hi*lo
                    mma_bf16(acc[mf][nf], a[1][mf], bh0, bh1);  // lo*hi
                }
        }
    }
}

template <int K1, int K2, bool WF32, bool F32RELU, bool WHILO>
__global__ __launch_bounds__(256, 2) void gemm_mma(
    const bf16* __restrict__ A1hi, const bf16* __restrict__ A1lo,
    const bf16* __restrict__ A2hi, const bf16* __restrict__ A2lo,
    const bf16* __restrict__ W1hi, const bf16* __restrict__ W1lo,
    const bf16* __restrict__ W2hi, const bf16* __restrict__ W2lo,
    const float* __restrict__ bias,
    float* __restrict__ C, bf16* __restrict__ Ohi, bf16* __restrict__ Olo,
    int M, int N, int hilo_limit) {
    __shared__ bf16 sA[2 * BM][SLDA];
    __shared__ bf16 sW[2 * BN][SLDA];
    float acc[2][4][4];
#pragma unroll
    for (int i = 0; i < 2; i++)
#pragma unroll
        for (int j = 0; j < 4; j++)
#pragma unroll
            for (int k = 0; k < 4; k++) acc[i][j][k] = 0.f;

    int m0 = blockIdx.x * BM, n0 = blockIdx.y * BN;

    mma_phase<K1>(A1hi, A1lo, W1hi, W1lo, M, m0, n0, sA, sW, acc);
    if constexpr (K2 > 0)
        mma_phase<K2>(A2hi, A2lo, W2hi, W2lo, M, m0, n0, sA, sW, acc);

    int t = threadIdx.x, lane = t & 31, warp = t >> 5;
    int wm = (warp & 3) * 32, wn = (warp >> 2) * 32;
#pragma unroll
    for (int mf = 0; mf < 2; mf++) {
        int row0 = m0 + wm + mf * 16 + (lane >> 2);
        int row1 = row0 + 8;
#pragma unroll
        for (int nf = 0; nf < 4; nf++) {
            int col = n0 + wn + nf * 8 + (lane & 3) * 2;
            float b0 = bias[col], b1 = bias[col + 1];
            float v00 = acc[mf][nf][0] + b0, v01 = acc[mf][nf][1] + b1;
            float v10 = acc[mf][nf][2] + b0, v11 = acc[mf][nf][3] + b1;
#pragma unroll
            for (int half = 0; half < 2; half++) {
                int row = half ? row1 : row0;
                float a0 = half ? v10 : v00;
                float a1 = half ? v11 : v01;
                if (row < M) {
                    if (WF32) {
                        float o0 = F32RELU ? fmaxf(a0, 0.f) : a0;
                        float o1 = F32RELU ? fmaxf(a1, 0.f) : a1;
                        *(float2*)&C[(size_t)row * N + col] = make_float2(o0, o1);
                    }
                    if (WHILO && row < hilo_limit) {
                        float r0 = fmaxf(a0, 0.f), r1 = fmaxf(a1, 0.f);
                        bf16 h0, l0, h1, l1;
                        split2(r0, h0, l0); split2(r1, h1, l1);
                        __nv_bfloat162 hv; hv.x = h0; hv.y = h1;
                        __nv_bfloat162 lv; lv.x = l0; lv.y = l1;
                        *(__nv_bfloat162*)&Ohi[(size_t)row * N + col] = hv;
                        *(__nv_bfloat162*)&Olo[(size_t)row * N + col] = lv;
                    }
                }
            }
        }
    }
}

// ---------------- log_softmax over rows of 128 ----------------
__global__ void logsoftmax_kernel(const float* __restrict__ logits, float* __restrict__ out) {
    __shared__ float red[128];
    int row = blockIdx.x;
    int t = threadIdx.x;
    float v = logits[row * F_OUT + t];
    red[t] = v;
    __syncthreads();
    for (int off = 64; off > 0; off >>= 1) {
        if (t < off) red[t] = fmaxf(red[t], red[t + off]);
        __syncthreads();
    }
    float mx = red[0];
    __syncthreads();
    red[t] = expf(v - mx);
    __syncthreads();
    for (int off = 64; off > 0; off >>= 1) {
        if (t < off) red[t] += red[t + off];
        __syncthreads();
    }
    float lse = logf(red[0]);
    out[row * F_OUT + t] = v - mx - lse;
}

// ---------------- launch ----------------
extern "C" void kernel_launch(void* const* d_in, const int* in_sizes, int n_in,
                              void* d_out, int out_size) {
    const float* x   = (const float*)d_in[0];
    const int*   ei1 = (const int*)d_in[1];
    const int*   ei2 = (const int*)d_in[2];
    const float* Wl1 = (const float*)d_in[3];
    const float* bl1 = (const float*)d_in[4];
    const float* Wr1 = (const float*)d_in[5];
    const float* Wl2 = (const float*)d_in[6];
    const float* bl2 = (const float*)d_in[7];
    const float* Wr2 = (const float*)d_in[8];
    const float* W1  = (const float*)d_in[9];
    const float* b1  = (const float*)d_in[10];
    const float* W2  = (const float*)d_in[11];
    const float* b2  = (const float*)d_in[12];

    int E1 = in_sizes[1] / 2;
    int E2 = in_sizes[2] / 2;
    const int* src1 = ei1;
    const int* tgt1 = ei1 + E1;
    const int* src2 = ei2;
    const int* tgt2 = ei2 + E2;

    float* out_ls  = (float*)d_out;                     // [10000,128]
    float* out_emb = (float*)d_out + N_TGT2 * F_OUT;    // [10000,192]

    // symbol addresses
    bf16 *p_xhi, *p_xlo, *p_m1hi, *p_m1lo, *p_h1hi, *p_h1lo, *p_m2hi, *p_m2lo;
    bf16 *p_h2hi, *p_h2lo, *p_erhi, *p_erlo;
    bf16 *p_wl1h, *p_wl1l, *p_wr1h, *p_wr1l, *p_wl2h, *p_wl2l, *p_wr2h, *p_wr2l;
    bf16 *p_w1h, *p_w1l, *p_w2h, *p_w2l;
    float *p_h1, *p_logits;
    int *p_cnt, *p_offs1, *p_offs2, *p_csr1, *p_csr2;
    cudaGetSymbolAddress((void**)&p_xhi,  g_x_hi);  cudaGetSymbolAddress((void**)&p_xlo,  g_x_lo);
    cudaGetSymbolAddress((void**)&p_m1hi, g_m1_hi); cudaGetSymbolAddress((void**)&p_m1lo, g_m1_lo);
    cudaGetSymbolAddress((void**)&p_h1hi, g_h1_hi); cudaGetSymbolAddress((void**)&p_h1lo, g_h1_lo);
    cudaGetSymbolAddress((void**)&p_m2hi, g_m2_hi); cudaGetSymbolAddress((void**)&p_m2lo, g_m2_lo);
    cudaGetSymbolAddress((void**)&p_h2hi, g_h2_hi); cudaGetSymbolAddress((void**)&p_h2lo, g_h2_lo);
    cudaGetSymbolAddress((void**)&p_erhi, g_er_hi); cudaGetSymbolAddress((void**)&p_erlo, g_er_lo);
    cudaGetSymbolAddress((void**)&p_wl1h, g_wl1_hi); cudaGetSymbolAddress((void**)&p_wl1l, g_wl1_lo);
    cudaGetSymbolAddress((void**)&p_wr1h, g_wr1_hi); cudaGetSymbolAddress((void**)&p_wr1l, g_wr1_lo);
    cudaGetSymbolAddress((void**)&p_wl2h, g_wl2_hi); cudaGetSymbolAddress((void**)&p_wl2l, g_wl2_lo);
    cudaGetSymbolAddress((void**)&p_wr2h, g_wr2_hi); cudaGetSymbolAddress((void**)&p_wr2l, g_wr2_lo);
    cudaGetSymbolAddress((void**)&p_w1h,  g_w1_hi);  cudaGetSymbolAddress((void**)&p_w1l,  g_w1_lo);
    cudaGetSymbolAddress((void**)&p_w2h,  g_w2_hi);  cudaGetSymbolAddress((void**)&p_w2l,  g_w2_lo);
    cudaGetSymbolAddress((void**)&p_h1,     g_h1);
    cudaGetSymbolAddress((void**)&p_logits, g_logits);
    cudaGetSymbolAddress((void**)&p_cnt,   g_cnt);
    cudaGetSymbolAddress((void**)&p_offs1, g_offs1);
    cudaGetSymbolAddress((void**)&p_offs2, g_offs2);
    cudaGetSymbolAddress((void**)&p_csr1,  g_csr1);
    cudaGetSymbolAddress((void**)&p_csr2,  g_csr2);

    // ---- precompute splits (weights + x[:50k]) ----
    {
        const int total = 2 * (F_HID * F_IN) + 3 * (F_HID * F_HID) + F_OUT * F_HID;
        split_weights_kernel<<<(total + 255) / 256, 256>>>(Wl1, Wr1, Wl2, Wr2, W1, W2);
    }
    split_x_kernel<<<(N_TGT1 * F_IN + 255) / 256, 256>>>(x);

    // ---- layer 1: CSR + mean aggregate (emits hi/lo planes) ----
    cudaMemsetAsync(p_cnt, 0, N_TGT1 * sizeof(int));
    hist_kernel<<<(E1 + 255) / 256, 256>>>(tgt1, E1, p_cnt);
    scan_kernel<<<1, 1024>>>(p_cnt, p_offs1, N_TGT1);
    cudaMemsetAsync(p_cnt, 0, N_TGT1 * sizeof(int));
    fill_kernel<<<(E1 + 255) / 256, 256>>>(src1, tgt1, E1, p_offs1, p_cnt, p_csr1);
    aggregate_hilo<F_IN><<<N_TGT1, F_IN>>>(x, p_csr1, p_offs1, p_m1hi, p_m1lo);

    // h1 = relu(mean1 @ Wl1^T + x[:50k] @ Wr1^T + bl1)  -> fp32 (for agg2) + hi/lo (first 10k rows)
    gemm_mma<F_IN, F_IN, true, true, true>
        <<<dim3((N_TGT1 + BM - 1) / BM, F_HID / BN), 256>>>(
            p_m1hi, p_m1lo, p_xhi, p_xlo, p_wl1h, p_wl1l, p_wr1h, p_wr1l,
            bl1, p_h1, p_h1hi, p_h1lo, N_TGT1, F_HID, N_TGT2);

    // ---- layer 2 ----
    cudaMemsetAsync(p_cnt, 0, N_TGT2 * sizeof(int));
    hist_kernel<<<(E2 + 255) / 256, 256>>>(tgt2, E2, p_cnt);
    scan_kernel<<<1, 1024>>>(p_cnt, p_offs2, N_TGT2);
    cudaMemsetAsync(p_cnt, 0, N_TGT2 * sizeof(int));
    fill_kernel<<<(E2 + 255) / 256, 256>>>(src2, tgt2, E2, p_offs2, p_cnt, p_csr2);
    aggregate_hilo<F_HID><<<N_TGT2, F_HID>>>(p_h1, p_csr2, p_offs2, p_m2hi, p_m2lo);

    // h2 = relu(mean2 @ Wl2^T + h1[:10k] @ Wr2^T + bl2) -> hi/lo only
    gemm_mma<F_HID, F_HID, false, false, true>
        <<<dim3((N_TGT2 + BM - 1) / BM, F_HID / BN), 256>>>(
            p_m2hi, p_m2lo, p_h1hi, p_h1lo, p_wl2h, p_wl2l, p_wr2h, p_wr2l,
            bl2, nullptr, p_h2hi, p_h2lo, N_TGT2, F_HID, N_TGT2);

    // embedding = h2 @ W1^T + b1 -> fp32 (to out) + relu hi/lo (for GEMM4)
    gemm_mma<F_HID, 0, true, false, true>
        <<<dim3((N_TGT2 + BM - 1) / BM, F_HID / BN), 256>>>(
            p_h2hi, p_h2lo, nullptr, nullptr, p_w1h, p_w1l, nullptr, nullptr,
            b1, out_emb, p_erhi, p_erlo, N_TGT2, F_HID, N_TGT2);

    // logits = relu(emb) @ W2^T + b2 -> fp32
    gemm_mma<F_HID, 0, true, false, false>
        <<<dim3((N_TGT2 + BM - 1) / BM, F_OUT / BN), 256>>>(
            p_erhi, p_erlo, nullptr, nullptr, p_w2h, p_w2l, nullptr, nullptr,
            b2, p_logits, nullptr, nullptr, N_TGT2, F_OUT, 0);

    logsoftmax_kernel<<<N_TGT2, F_OUT>>>(p_logits, out_ls);
}

// round 3
// speedup vs baseline: 1.2902x; 1.1841x over previous
#include <cuda_runtime.h>
#include <cuda_bf16.h>
#include <math.h>
#include <stdint.h>

typedef __nv_bfloat16 bf16;

#define N_SRC1 200000
#define N_TGT1 50000
#define N_TGT2 10000
#define F_IN   256
#define F_HID  192
#define F_OUT  128
#define E1_MAX 1000000
#define E2_MAX 300000

// ---------------- scratch ----------------
__device__ bf16 g_m1_hi[N_TGT1 * F_IN];
__device__ bf16 g_m1_lo[N_TGT1 * F_IN];
__device__ float g_h1[(size_t)N_TGT1 * F_HID];
__device__ bf16 g_h1_hi[N_TGT2 * F_HID];
__device__ bf16 g_h1_lo[N_TGT2 * F_HID];
__device__ bf16 g_m2_hi[N_TGT2 * F_HID];
__device__ bf16 g_m2_lo[N_TGT2 * F_HID];
__device__ bf16 g_h2_hi[N_TGT2 * F_HID];
__device__ bf16 g_h2_lo[N_TGT2 * F_HID];
__device__ bf16 g_er_hi[N_TGT2 * F_HID];
__device__ bf16 g_er_lo[N_TGT2 * F_HID];
__device__ float g_logits[N_TGT2 * F_OUT];
// weight hi/lo planes
__device__ bf16 g_wl1_hi[F_HID * F_IN],  g_wl1_lo[F_HID * F_IN];
__device__ bf16 g_wr1_hi[F_HID * F_IN],  g_wr1_lo[F_HID * F_IN];
__device__ bf16 g_wl2_hi[F_HID * F_HID], g_wl2_lo[F_HID * F_HID];
__device__ bf16 g_wr2_hi[F_HID * F_HID], g_wr2_lo[F_HID * F_HID];
__device__ bf16 g_w1_hi[F_HID * F_HID],  g_w1_lo[F_HID * F_HID];
__device__ bf16 g_w2_hi[F_OUT * F_HID],  g_w2_lo[F_OUT * F_HID];
// CSR
__device__ int g_cnt[N_TGT1];
__device__ int g_bsum[1024];
__device__ int g_offs1[N_TGT1 + 1];
__device__ int g_offs2[N_TGT2 + 1];
__device__ int g_csr1[E1_MAX];
__device__ int g_csr2[E2_MAX];

// ---------------- CSR build ----------------
__global__ void hist_kernel(const int* __restrict__ tgt, int E, int* __restrict__ cnt) {
    int i = blockIdx.x * blockDim.x + threadIdx.x;
    if (i < E) atomicAdd(&cnt[tgt[i]], 1);
}

// hierarchical scan: (1) per-block sums
#define SCAN_B 256
__global__ void block_sum_kernel(const int* __restrict__ cnt, int n, int* __restrict__ bsum) {
    __shared__ int sm[SCAN_B];
    int t = threadIdx.x;
    int i = blockIdx.x * SCAN_B + t;
    sm[t] = (i < n) ? cnt[i] : 0;
    __syncthreads();
    for (int off = SCAN_B / 2; off > 0; off >>= 1) {
        if (t < off) sm[t] += sm[t + off];
        __syncthreads();
    }
    if (t == 0) bsum[blockIdx.x] = sm[0];
}

// (2) single-block exclusive scan of G <= 1024 block sums; writes total to *total
__global__ void scan_bsum_kernel(int* __restrict__ bsum, int G, int* __restrict__ total) {
    __shared__ int sm[1024];
    int t = threadIdx.x;
    int v = (t < G) ? bsum[t] : 0;
    sm[t] = v;
    __syncthreads();
    for (int off = 1; off < 1024; off <<= 1) {
        int u = (t >= off) ? sm[t - off] : 0;
        __syncthreads();
        sm[t] += u;
        __syncthreads();
    }
    if (t < G) bsum[t] = sm[t] - v;           // exclusive
    if (t == 1023) *total = sm[1023];          // grand total
}

// (3) per-block exclusive scan + add block prefix -> offs
__global__ void scatter_offs_kernel(const int* __restrict__ cnt, int n,
                                    const int* __restrict__ bsum, int* __restrict__ offs) {
    __shared__ int sm[SCAN_B];
    int t = threadIdx.x;
    int i = blockIdx.x * SCAN_B + t;
    int v = (i < n) ? cnt[i] : 0;
    sm[t] = v;
    __syncthreads();
    for (int off = 1; off < SCAN_B; off <<= 1) {
        int u = (t >= off) ? sm[t - off] : 0;
        __syncthreads();
        sm[t] += u;
        __syncthreads();
    }
    if (i < n) offs[i] = bsum[blockIdx.x] + sm[t] - v;
}

__global__ void fill_kernel(const int* __restrict__ src, const int* __restrict__ tgt, int E,
                            const int* __restrict__ offs, int* __restrict__ cursor,
                            int* __restrict__ csr) {
    int i = blockIdx.x * blockDim.x + threadIdx.x;
    if (i < E) {
        int t = tgt[i];
        int p = atomicAdd(&cursor[t], 1);
        csr[offs[t] + p] = src[i];
    }
}

// ---------------- splits ----------------
__device__ __forceinline__ void split2(float v, bf16& h, bf16& l) {
    bf16 hh = __float2bfloat16_rn(v);
    h = hh;
    l = __float2bfloat16_rn(v - __bfloat162float(hh));
}

__global__ void split_weights_kernel(const float* __restrict__ wl1, const float* __restrict__ wr1,
                                     const float* __restrict__ wl2, const float* __restrict__ wr2,
                                     const float* __restrict__ w1,  const float* __restrict__ w2) {
    int i = blockIdx.x * 256 + threadIdx.x;
    const int A = F_HID * F_IN;
    const int B = F_HID * F_HID;
    const int C = F_OUT * F_HID;
    float v; bf16 *hp, *lp; int o;
    if      (i < A)             { o = i;               v = wl1[o]; hp = g_wl1_hi; lp = g_wl1_lo; }
    else if (i < 2*A)           { o = i - A;           v = wr1[o]; hp = g_wr1_hi; lp = g_wr1_lo; }
    else if (i < 2*A + B)       { o = i - 2*A;         v = wl2[o]; hp = g_wl2_hi; lp = g_wl2_lo; }
    else if (i < 2*A + 2*B)     { o = i - 2*A - B;     v = wr2[o]; hp = g_wr2_hi; lp = g_wr2_lo; }
    else if (i < 2*A + 3*B)     { o = i - 2*A - 2*B;   v = w1[o];  hp = g_w1_hi;  lp = g_w1_lo; }
    else if (i < 2*A + 3*B + C) { o = i - 2*A - 3*B;   v = w2[o];  hp = g_w2_hi;  lp = g_w2_lo; }
    else return;
    bf16 h, l; split2(v, h, l);
    hp[o] = h; lp[o] = l;
}

// ---------------- segment mean -> hi/lo planes (8-wide edge unroll) ----------------
template <int F>
__global__ void aggregate_hilo(const float* __restrict__ X, const int* __restrict__ csr,
                               const int* __restrict__ offs,
                               bf16* __restrict__ hi, bf16* __restrict__ lo) {
    int node = blockIdx.x;
    int t = threadIdx.x;
    int s = offs[node], e = offs[node + 1];
    float acc = 0.0f;
    int j = s;
    for (; j + 7 < e; j += 8) {
        int i0 = __ldg(&csr[j]),     i1 = __ldg(&csr[j + 1]);
        int i2 = __ldg(&csr[j + 2]), i3 = __ldg(&csr[j + 3]);
        int i4 = __ldg(&csr[j + 4]), i5 = __ldg(&csr[j + 5]);
        int i6 = __ldg(&csr[j + 6]), i7 = __ldg(&csr[j + 7]);
        float v0 = X[(size_t)i0 * F + t];
        float v1 = X[(size_t)i1 * F + t];
        float v2 = X[(size_t)i2 * F + t];
        float v3 = X[(size_t)i3 * F + t];
        float v4 = X[(size_t)i4 * F + t];
        float v5 = X[(size_t)i5 * F + t];
        float v6 = X[(size_t)i6 * F + t];
        float v7 = X[(size_t)i7 * F + t];
        acc += ((v0 + v1) + (v2 + v3)) + ((v4 + v5) + (v6 + v7));
    }
    for (; j < e; j++) acc += X[(size_t)__ldg(&csr[j]) * F + t];
    int deg = e - s;
    float m = acc * (1.0f / (float)(deg > 1 ? deg : 1));
    bf16 h, l; split2(m, h, l);
    size_t o = (size_t)node * F + t;
    hi[o] = h; lo[o] = l;
}

// ---------------- bf16x3 tensor-core GEMM ----------------
#define BM 128
#define BN 64
#define BKT 32
#define SLDA 40

__device__ __forceinline__ void ldsm4(uint32_t r[4], uint32_t addr) {
    asm volatile("ldmatrix.sync.aligned.m8n8.x4.shared.b16 {%0,%1,%2,%3}, [%4];"
                 : "=r"(r[0]), "=r"(r[1]), "=r"(r[2]), "=r"(r[3]) : "r"(addr));
}
__device__ __forceinline__ void mma_bf16(float d[4], const uint32_t a[4], uint32_t b0, uint32_t b1) {
    asm volatile("mma.sync.aligned.m16n8k16.row.col.f32.bf16.bf16.f32 "
                 "{%0,%1,%2,%3},{%4,%5,%6,%7},{%8,%9},{%0,%1,%2,%3};"
                 : "+f"(d[0]), "+f"(d[1]), "+f"(d[2]), "+f"(d[3])
                 : "r"(a[0]), "r"(a[1]), "r"(a[2]), "r"(a[3]), "r"(b0), "r"(b1));
}

// pack 8 floats into hi/lo uint4s (8 bf16 each)
__device__ __forceinline__ void split8(const float f[8], uint4& h, uint4& l) {
    __nv_bfloat162 hh[4], ll[4];
#pragma unroll
    for (int i = 0; i < 4; i++) {
        bf16 h0, l0, h1, l1;
        split2(f[2 * i], h0, l0);
        split2(f[2 * i + 1], h1, l1);
        hh[i].x = h0; hh[i].y = h1;
        ll[i].x = l0; ll[i].y = l1;
    }
    h = *(uint4*)hh;
    l = *(uint4*)ll;
}

// F32SRC: A supplied as fp32 (Ahi reinterpreted as float*), split on the fly.
template <int K, bool F32SRC>
__device__ __forceinline__ void mma_phase(const void* __restrict__ Ahi_v, const bf16* __restrict__ Alo,
                                          const bf16* __restrict__ Whi, const bf16* __restrict__ Wlo,
                                          int M, int m0, int n0,
                                          bf16 (*sA)[SLDA], bf16 (*sW)[SLDA],
                                          float acc[2][4][4]) {
    int t = threadIdx.x;
    int lane = t & 31, warp = t >> 5;
    int wm = (warp & 3) * 32, wn = (warp >> 2) * 32;
    uint32_t sA_u = (uint32_t)__cvta_generic_to_shared(&sA[0][0]);
    uint32_t sW_u = (uint32_t)__cvta_generic_to_shared(&sW[0][0]);

    int ar = t >> 1, ac = (t & 1) * 16;   // A: 128 rows x 32 cols per plane
    int wr = t >> 2, wc = (t & 3) * 8;    // W: 64 rows x 32 cols per plane

    uint32_t a_off[2][2], b_off[2][2];
#pragma unroll
    for (int p = 0; p < 2; p++) {
#pragma unroll
        for (int mf = 0; mf < 2; mf++)
            a_off[p][mf] = sA_u + (uint32_t)(((p * BM + wm + mf * 16 + (lane & 15)) * SLDA + ((lane >> 4) * 8)) * 2);
#pragma unroll
        for (int np = 0; np < 2; np++)
            b_off[p][np] = sW_u + (uint32_t)(((p * BN + wn + np * 16 + (lane & 7) + ((lane >> 4) * 8)) * SLDA +
                                             (((lane >> 3) & 1) * 8)) * 2);
    }

    for (int kt = 0; kt < K; kt += BKT) {
        __syncthreads();
        {
            bool av = (m0 + ar) < M;
            uint4 h0, h1, l0, l1;
            if (F32SRC) {
                const float* Xf = (const float*)Ahi_v;
                float f[16];
                if (av) {
                    size_t abase = (size_t)(m0 + ar) * K + kt + ac;
#pragma unroll
                    for (int q = 0; q < 4; q++)
                        *(float4*)&f[4 * q] = *(const float4*)(Xf + abase + 4 * q);
                } else {
#pragma unroll
                    for (int q = 0; q < 16; q++) f[q] = 0.f;
                }
                split8(&f[0], h0, l0);
                split8(&f[8], h1, l1);
            } else {
                const bf16* Ahi = (const bf16*)Ahi_v;
                uint4 z = make_uint4(0, 0, 0, 0);
                size_t abase = (size_t)(m0 + ar) * K + kt + ac;
                h0 = av ? *(const uint4*)(Ahi + abase)     : z;
                h1 = av ? *(const uint4*)(Ahi + abase + 8) : z;
                l0 = av ? *(const uint4*)(Alo + abase)     : z;
                l1 = av ? *(const uint4*)(Alo + abase + 8) : z;
            }
            *(uint4*)&sA[ar][ac]          = h0;
            *(uint4*)&sA[ar][ac + 8]      = h1;
            *(uint4*)&sA[BM + ar][ac]     = l0;
            *(uint4*)&sA[BM + ar][ac + 8] = l1;
            size_t wbase = (size_t)(n0 + wr) * K + kt + wc;
            *(uint4*)&sW[wr][wc]      = *(const uint4*)(Whi + wbase);
            *(uint4*)&sW[BN + wr][wc] = *(const uint4*)(Wlo + wbase);
        }
        __syncthreads();
#pragma unroll
        for (int ks = 0; ks < 2; ks++) {
            uint32_t a[2][2][4], b[2][2][4];
#pragma unroll
            for (int p = 0; p < 2; p++) {
#pragma unroll
                for (int mf = 0; mf < 2; mf++) ldsm4(a[p][mf], a_off[p][mf] + ks * 32);
#pragma unroll
                for (int np = 0; np < 2; np++) ldsm4(b[p][np], b_off[p][np] + ks * 32);
            }
#pragma unroll
            for (int mf = 0; mf < 2; mf++)
#pragma unroll
                for (int nf = 0; nf < 4; nf++) {
                    uint32_t bh0 = b[0][nf >> 1][(nf & 1) * 2], bh1 = b[0][nf >> 1][(nf & 1) * 2 + 1];
                    uint32_t bl0 = b[1][nf >> 1][(nf & 1) * 2], bl1 = b[1][nf >> 1][(nf & 1) * 2 + 1];
                    mma_bf16(acc[mf][nf], a[0][mf], bh0, bh1);  // hi*hi
                    mma_bf16(acc[mf][nf], a[0][mf], bl0, bl1);  // hi*lo
                    mma_bf16(acc[mf][nf], a[1][mf], bh0, bh1);  // lo*hi
                }
        }
    }
}

template <int K1, int K2, bool A2F32, bool WF32, bool F32RELU, bool WHILO>
__global__ __launch_bounds__(256, 2) void gemm_mma(
    const bf16* __restrict__ A1hi, const bf16* __restrict__ A1lo,
    const void* __restrict__ A2hi, const bf16* __restrict__ A2lo,
    const bf16* __restrict__ W1hi, const bf16* __restrict__ W1lo,
    const bf16* __restrict__ W2hi, const bf16* __restrict__ W2lo,
    const float* __restrict__ bias,
    float* __restrict__ C, bf16* __restrict__ Ohi, bf16* __restrict__ Olo,
    int M, int N, int hilo_limit) {
    __shared__ bf16 sA[2 * BM][SLDA];
    __shared__ bf16 sW[2 * BN][SLDA];
    float acc[2][4][4];
#pragma unroll
    for (int i = 0; i < 2; i++)
#pragma unroll
        for (int j = 0; j < 4; j++)
#pragma unroll
            for (int k = 0; k < 4; k++) acc[i][j][k] = 0.f;

    int m0 = blockIdx.x * BM, n0 = blockIdx.y * BN;

    mma_phase<K1, false>(A1hi, A1lo, W1hi, W1lo, M, m0, n0, sA, sW, acc);
    if constexpr (K2 > 0)
        mma_phase<K2, A2F32>(A2hi, A2lo, W2hi, W2lo, M, m0, n0, sA, sW, acc);

    int t = threadIdx.x, lane = t & 31, warp = t >> 5;
    int wm = (warp & 3) * 32, wn = (warp >> 2) * 32;
#pragma unroll
    for (int mf = 0; mf < 2; mf++) {
        int row0 = m0 + wm + mf * 16 + (lane >> 2);
        int row1 = row0 + 8;
#pragma unroll
        for (int nf = 0; nf < 4; nf++) {
            int col = n0 + wn + nf * 8 + (lane & 3) * 2;
            float b0 = bias[col], b1 = bias[col + 1];
            float v00 = acc[mf][nf][0] + b0, v01 = acc[mf][nf][1] + b1;
            float v10 = acc[mf][nf][2] + b0, v11 = acc[mf][nf][3] + b1;
#pragma unroll
            for (int half = 0; half < 2; half++) {
                int row = half ? row1 : row0;
                float a0 = half ? v10 : v00;
                float a1 = half ? v11 : v01;
                if (row < M) {
                    if (WF32) {
                        float o0 = F32RELU ? fmaxf(a0, 0.f) : a0;
                        float o1 = F32RELU ? fmaxf(a1, 0.f) : a1;
                        *(float2*)&C[(size_t)row * N + col] = make_float2(o0, o1);
                    }
                    if (WHILO && row < hilo_limit) {
                        float r0 = fmaxf(a0, 0.f), r1 = fmaxf(a1, 0.f);
                        bf16 h0, l0, h1, l1;
                        split2(r0, h0, l0); split2(r1, h1, l1);
                        __nv_bfloat162 hv; hv.x = h0; hv.y = h1;
                        __nv_bfloat162 lv; lv.x = l0; lv.y = l1;
                        *(__nv_bfloat162*)&Ohi[(size_t)row * N + col] = hv;
                        *(__nv_bfloat162*)&Olo[(size_t)row * N + col] = lv;
                    }
                }
            }
        }
    }
}

// ---------------- log_softmax ----------------
__global__ void logsoftmax_kernel(const float* __restrict__ logits, float* __restrict__ out) {
    __shared__ float red[128];
    int row = blockIdx.x;
    int t = threadIdx.x;
    float v = logits[row * F_OUT + t];
    red[t] = v;
    __syncthreads();
    for (int off = 64; off > 0; off >>= 1) {
        if (t < off) red[t] = fmaxf(red[t], red[t + off]);
        __syncthreads();
    }
    float mx = red[0];
    __syncthreads();
    red[t] = expf(v - mx);
    __syncthreads();
    for (int off = 64; off > 0; off >>= 1) {
        if (t < off) red[t] += red[t + off];
        __syncthreads();
    }
    float lse = logf(red[0]);
    out[row * F_OUT + t] = v - mx - lse;
}

// ---------------- launch ----------------
extern "C" void kernel_launch(void* const* d_in, const int* in_sizes, int n_in,
                              void* d_out, int out_size) {
    const float* x   = (const float*)d_in[0];
    const int*   ei1 = (const int*)d_in[1];
    const int*   ei2 = (const int*)d_in[2];
    const float* Wl1 = (const float*)d_in[3];
    const float* bl1 = (const float*)d_in[4];
    const float* Wr1 = (const float*)d_in[5];
    const float* Wl2 = (const float*)d_in[6];
    const float* bl2 = (const float*)d_in[7];
    const float* Wr2 = (const float*)d_in[8];
    const float* W1  = (const float*)d_in[9];
    const float* b1  = (const float*)d_in[10];
    const float* W2  = (const float*)d_in[11];
    const float* b2  = (const float*)d_in[12];

    int E1 = in_sizes[1] / 2;
    int E2 = in_sizes[2] / 2;
    const int* src1 = ei1;
    const int* tgt1 = ei1 + E1;
    const int* src2 = ei2;
    const int* tgt2 = ei2 + E2;

    float* out_ls  = (float*)d_out;
    float* out_emb = (float*)d_out + N_TGT2 * F_OUT;

    bf16 *p_m1hi, *p_m1lo, *p_h1hi, *p_h1lo, *p_m2hi, *p_m2lo;
    bf16 *p_h2hi, *p_h2lo, *p_erhi, *p_erlo;
    bf16 *p_wl1h, *p_wl1l, *p_wr1h, *p_wr1l, *p_wl2h, *p_wl2l, *p_wr2h, *p_wr2l;
    bf16 *p_w1h, *p_w1l, *p_w2h, *p_w2l;
    float *p_h1, *p_logits;
    int *p_cnt, *p_bsum, *p_offs1, *p_offs2, *p_csr1, *p_csr2;
    cudaGetSymbolAddress((void**)&p_m1hi, g_m1_hi); cudaGetSymbolAddress((void**)&p_m1lo, g_m1_lo);
    cudaGetSymbolAddress((void**)&p_h1hi, g_h1_hi); cudaGetSymbolAddress((void**)&p_h1lo, g_h1_lo);
    cudaGetSymbolAddress((void**)&p_m2hi, g_m2_hi); cudaGetSymbolAddress((void**)&p_m2lo, g_m2_lo);
    cudaGetSymbolAddress((void**)&p_h2hi, g_h2_hi); cudaGetSymbolAddress((void**)&p_h2lo, g_h2_lo);
    cudaGetSymbolAddress((void**)&p_erhi, g_er_hi); cudaGetSymbolAddress((void**)&p_erlo, g_er_lo);
    cudaGetSymbolAddress((void**)&p_wl1h, g_wl1_hi); cudaGetSymbolAddress((void**)&p_wl1l, g_wl1_lo);
    cudaGetSymbolAddress((void**)&p_wr1h, g_wr1_hi); cudaGetSymbolAddress((void**)&p_wr1l, g_wr1_lo);
    cudaGetSymbolAddress((void**)&p_wl2h, g_wl2_hi); cudaGetSymbolAddress((void**)&p_wl2l, g_wl2_lo);
    cudaGetSymbolAddress((void**)&p_wr2h, g_wr2_hi); cudaGetSymbolAddress((void**)&p_wr2l, g_wr2_lo);
    cudaGetSymbolAddress((void**)&p_w1h,  g_w1_hi);  cudaGetSymbolAddress((void**)&p_w1l,  g_w1_lo);
    cudaGetSymbolAddress((void**)&p_w2h,  g_w2_hi);  cudaGetSymbolAddress((void**)&p_w2l,  g_w2_lo);
    cudaGetSymbolAddress((void**)&p_h1,     g_h1);
    cudaGetSymbolAddress((void**)&p_logits, g_logits);
    cudaGetSymbolAddress((void**)&p_cnt,   g_cnt);
    cudaGetSymbolAddress((void**)&p_bsum,  g_bsum);
    cudaGetSymbolAddress((void**)&p_offs1, g_offs1);
    cudaGetSymbolAddress((void**)&p_offs2, g_offs2);
    cudaGetSymbolAddress((void**)&p_csr1,  g_csr1);
    cudaGetSymbolAddress((void**)&p_csr2,  g_csr2);

    // ---- weight splits ----
    {
        const int total = 2 * (F_HID * F_IN) + 3 * (F_HID * F_HID) + F_OUT * F_HID;
        split_weights_kernel<<<(total + 255) / 256, 256>>>(Wl1, Wr1, Wl2, Wr2, W1, W2);
    }

    const int G1 = (N_TGT1 + SCAN_B - 1) / SCAN_B;   // 196
    const int G2 = (N_TGT2 + SCAN_B - 1) / SCAN_B;   // 40

    // ---- layer 1 CSR ----
    cudaMemsetAsync(p_cnt, 0, N_TGT1 * sizeof(int));
    hist_kernel<<<(E1 + 255) / 256, 256>>>(tgt1, E1, p_cnt);
    block_sum_kernel<<<G1, SCAN_B>>>(p_cnt, N_TGT1, p_bsum);
    scan_bsum_kernel<<<1, 1024>>>(p_bsum, G1, p_offs1 + N_TGT1);
    scatter_offs_kernel<<<G1, SCAN_B>>>(p_cnt, N_TGT1, p_bsum, p_offs1);
    cudaMemsetAsync(p_cnt, 0, N_TGT1 * sizeof(int));
    fill_kernel<<<(E1 + 255) / 256, 256>>>(src1, tgt1, E1, p_offs1, p_cnt, p_csr1);
    aggregate_hilo<F_IN><<<N_TGT1, F_IN>>>(x, p_csr1, p_offs1, p_m1hi, p_m1lo);

    // h1 = relu(mean1 @ Wl1^T + x[:50k] @ Wr1^T + bl1)
    gemm_mma<F_IN, F_IN, true, true, true, true>
        <<<dim3((N_TGT1 + BM - 1) / BM, F_HID / BN), 256>>>(
            p_m1hi, p_m1lo, x, nullptr, p_wl1h, p_wl1l, p_wr1h, p_wr1l,
            bl1, p_h1, p_h1hi, p_h1lo, N_TGT1, F_HID, N_TGT2);

    // ---- layer 2 CSR ----
    cudaMemsetAsync(p_cnt, 0, N_TGT2 * sizeof(int));
    hist_kernel<<<(E2 + 255) / 256, 256>>>(tgt2, E2, p_cnt);
    block_sum_kernel<<<G2, SCAN_B>>>(p_cnt, N_TGT2, p_bsum);
    scan_bsum_kernel<<<1, 1024>>>(p_bsum, G2, p_offs2 + N_TGT2);
    scatter_offs_kernel<<<G2, SCAN_B>>>(p_cnt, N_TGT2, p_bsum, p_offs2);
    cudaMemsetAsync(p_cnt, 0, N_TGT2 * sizeof(int));
    fill_kernel<<<(E2 + 255) / 256, 256>>>(src2, tgt2, E2, p_offs2, p_cnt, p_csr2);
    aggregate_hilo<F_HID><<<N_TGT2, F_HID>>>(p_h1, p_csr2, p_offs2, p_m2hi, p_m2lo);

    // h2 = relu(mean2 @ Wl2^T + h1[:10k] @ Wr2^T + bl2)
    gemm_mma<F_HID, F_HID, false, false, false, true>
        <<<dim3((N_TGT2 + BM - 1) / BM, F_HID / BN), 256>>>(
            p_m2hi, p_m2lo, p_h1hi, p_h1lo, p_wl2h, p_wl2l, p_wr2h, p_wr2l,
            bl2, nullptr, p_h2hi, p_h2lo, N_TGT2, F_HID, N_TGT2);

    // embedding = h2 @ W1^T + b1
    gemm_mma<F_HID, 0, false, true, false, true>
        <<<dim3((N_TGT2 + BM - 1) / BM, F_HID / BN), 256>>>(
            p_h2hi, p_h2lo, nullptr, nullptr, p_w1h, p_w1l, nullptr, nullptr,
            b1, out_emb, p_erhi, p_erlo, N_TGT2, F_HID, N_TGT2);

    // logits = relu(emb) @ W2^T + b2
    gemm_mma<F_HID, 0, false, true, false, false>
        <<<dim3((N_TGT2 + BM - 1) / BM, F_OUT / BN), 256>>>(
            p_erhi, p_erlo, nullptr, nullptr, p_w2h, p_w2l, nullptr, nullptr,
            b2, p_logits, nullptr, nullptr, N_TGT2, F_OUT, 0);

    logsoftmax_kernel<<<N_TGT2, F_OUT>>>(p_logits, out_ls);
}